// round 2
// baseline (speedup 1.0000x reference)
#include <cuda_runtime.h>
#include <cstdint>

#define S_   64
#define W_   128
#define D_   256
#define HW_  256
#define G3W_ 768
#define HS_  512
#define G3S_ 1536
#define C_   13

// ---------------- scratch (device globals; no allocation allowed) ----------
__device__ float g_X [2097152];    // [w][s][d]           128*64*256
__device__ float g_GI[12582912];   // [d][w][s][768]      2*128*64*768
__device__ float g_H [4194304];    // [d][w][s][256]
__device__ float g_WE[4194304];    // [s][w][512]
__device__ float g_U [4194304];    // [s][w][512]
__device__ float g_ssum[S_*HS_];         // [s][512]
__device__ float g_GIS[2*S_*G3S_];       // [d][s][1536]
__device__ float g_SE[S_*1024];          // [s][1024]
__device__ float g_US[S_*1024];          // [s][1024]

// ---------------- helpers --------------------------------------------------
__device__ __forceinline__ unsigned su32(const void* p) {
    return (unsigned)__cvta_generic_to_shared(p);
}
__device__ __forceinline__ float sigm(float x) { return 1.f / (1.f + expf(-x)); }

// ---------------- 1. embedding gather --------------------------------------
__global__ void k_gather(const int* __restrict__ doc, const float* __restrict__ emb) {
    int q  = blockIdx.x * blockDim.x + threadIdx.x;   // over 524288 float4s
    int d4 = q & 63;
    int rs = q >> 6;            // = w*64 + s
    int s  = rs & 63, w = rs >> 6;
    int tok = doc[s * W_ + w];
    ((float4*)g_X)[q] = ((const float4*)emb)[(long)tok * 64 + d4];
}

// ---------------- 2. generic tiled GEMM: C = act(A @ B^T + bias) -----------
// A[M,K], B[N,K] (torch weight layout), C[M,N]. z = batch (dirs).
#define BM 64
#define BN 64
#define BK 32
__global__ __launch_bounds__(256) void k_gemm(
    const float* __restrict__ A, const float* __restrict__ B,
    const float* __restrict__ bias, float* __restrict__ C,
    int M, int N, int K, int actTanh,
    long sAz, long sBz, long sbz, long sCz)
{
    __shared__ float As[BK][BM + 1];
    __shared__ float Bs[BK][BN + 1];
    int t  = threadIdx.x;
    int tx = t & 15, ty = t >> 4;
    int z  = blockIdx.z;
    const float* Ab = A + z * sAz + (long)blockIdx.x * BM * K;
    const float* Bb = B + z * sBz + (long)blockIdx.y * BN * K;
    float acc[4][4] = {};
    for (int k0 = 0; k0 < K; k0 += BK) {
#pragma unroll
        for (int j = 0; j < 8; j++) {
            int idx = j * 256 + t;
            int m = idx >> 5, k = idx & 31;
            As[k][m] = Ab[(long)m * K + k0 + k];
            Bs[k][m] = Bb[(long)m * K + k0 + k];
        }
        __syncthreads();
#pragma unroll 8
        for (int k = 0; k < BK; k++) {
            float a0 = As[k][ty*4+0], a1 = As[k][ty*4+1], a2 = As[k][ty*4+2], a3 = As[k][ty*4+3];
            float b0 = Bs[k][tx*4+0], b1 = Bs[k][tx*4+1], b2 = Bs[k][tx*4+2], b3 = Bs[k][tx*4+3];
            acc[0][0]=fmaf(a0,b0,acc[0][0]); acc[0][1]=fmaf(a0,b1,acc[0][1]);
            acc[0][2]=fmaf(a0,b2,acc[0][2]); acc[0][3]=fmaf(a0,b3,acc[0][3]);
            acc[1][0]=fmaf(a1,b0,acc[1][0]); acc[1][1]=fmaf(a1,b1,acc[1][1]);
            acc[1][2]=fmaf(a1,b2,acc[1][2]); acc[1][3]=fmaf(a1,b3,acc[1][3]);
            acc[2][0]=fmaf(a2,b0,acc[2][0]); acc[2][1]=fmaf(a2,b1,acc[2][1]);
            acc[2][2]=fmaf(a2,b2,acc[2][2]); acc[2][3]=fmaf(a2,b3,acc[2][3]);
            acc[3][0]=fmaf(a3,b0,acc[3][0]); acc[3][1]=fmaf(a3,b1,acc[3][1]);
            acc[3][2]=fmaf(a3,b2,acc[3][2]); acc[3][3]=fmaf(a3,b3,acc[3][3]);
        }
        __syncthreads();
    }
    const float* bp = bias + z * sbz;
#pragma unroll
    for (int i = 0; i < 4; i++) {
        int m = blockIdx.x * BM + ty * 4 + i;
#pragma unroll
        for (int j = 0; j < 4; j++) {
            int n = blockIdx.y * BN + tx * 4 + j;
            float v = acc[i][j] + bp[n];
            if (actTanh) v = tanhf(v);
            C[z * sCz + (long)m * N + n] = v;
        }
    }
}

// ---------------- 3. word GRU recurrence (cluster of 4) --------------------
// grid.x = 128: cluster id = blockIdx/4 -> (dir = cid>>4, sentence group of 4 = cid&15)
// rank owns h dims [rank*64, rank*64+64). Wh slice (3 gates x 64 dims x 256) in SMEM.
// h (4 sentences x 256 dims, double-buffered) replicated per CTA; new h pushed
// to all 4 CTAs via DSMEM, step fenced by barrier.cluster (release/acquire).
#define PADK 260                                    // 260 % 32 == 4 -> conflict-free LDS.128
#define GRU_SMEM ((3*64*PADK + 2*4*256 + 192) * 4)  // 208640 B

extern __shared__ float smem_gru[];

__global__ void __cluster_dims__(4, 1, 1) __launch_bounds__(128, 1)
k_wordgru(const float* __restrict__ wWh, const float* __restrict__ wbh)
{
    float* Wsh  = smem_gru;                 // [3*64][PADK]
    float* hbuf = Wsh + 3 * 64 * PADK;      // [2][4][256]
    float* bhs  = hbuf + 2 * 4 * 256;       // [192]

    int rank = blockIdx.x & 3;
    int cid  = blockIdx.x >> 2;
    int d    = cid >> 4;
    int s0   = (cid & 15) * 4;
    int j0   = rank * 64;
    int tid  = threadIdx.x;

    // load Wh slice (rows g*256 + j0 + jj, all k) into padded SMEM
    const float4* w4g = (const float4*)wWh;
    for (int i = tid; i < 3 * 64 * 64; i += 128) {
        int g  = i >> 12;
        int r2 = i & 4095;
        int jj = r2 >> 6, k4 = r2 & 63;
        float4 v = w4g[((long)d * G3W_ + g * 256 + j0 + jj) * 64 + k4];
        *(float4*)&Wsh[(g * 64 + jj) * PADK + k4 * 4] = v;
    }
    for (int i = tid; i < 192; i += 128)
        bhs[i] = wbh[d * G3W_ + (i >> 6) * 256 + j0 + (i & 63)];
    for (int i = tid; i < 4 * 256; i += 128) hbuf[i] = 0.f;   // buffer 0 = h0
    __syncthreads();
    asm volatile("barrier.cluster.arrive.aligned;" ::: "memory");
    asm volatile("barrier.cluster.wait.aligned;"   ::: "memory");

    int spair = tid >> 6;          // 0..1 -> sentence pair
    int jj    = tid & 63;
    int sA = spair * 2, sB = sA + 1;
    int dim = j0 + jj;
    float bhr = bhs[jj], bhz = bhs[64 + jj], bhn = bhs[128 + jj];
    const float4* wR = (const float4*)&Wsh[( 0 + jj) * PADK];
    const float4* wZ = (const float4*)&Wsh[( 64 + jj) * PADK];
    const float4* wN = (const float4*)&Wsh[(128 + jj) * PADK];

    for (int w = 0; w < W_; w++) {
        int cur = w & 1, nxt = cur ^ 1;
        long gibA = ((long)(d * W_ + w) * S_ + (s0 + sA)) * G3W_;
        long gibB = ((long)(d * W_ + w) * S_ + (s0 + sB)) * G3W_;
        float giRA = g_GI[gibA + dim], giZA = g_GI[gibA + 256 + dim], giNA = g_GI[gibA + 512 + dim];
        float giRB = g_GI[gibB + dim], giZB = g_GI[gibB + 256 + dim], giNB = g_GI[gibB + 512 + dim];

        const float4* hA = (const float4*)&hbuf[(cur * 4 + sA) * 256];
        const float4* hB = (const float4*)&hbuf[(cur * 4 + sB) * 256];
        float aRA = 0, aZA = 0, aNA = 0, aRB = 0, aZB = 0, aNB = 0;
#pragma unroll 8
        for (int k4 = 0; k4 < 64; k4++) {
            float4 wr = wR[k4], wz = wZ[k4], wn = wN[k4];
            float4 ha = hA[k4], hb = hB[k4];
            aRA = fmaf(wr.x, ha.x, aRA); aRA = fmaf(wr.y, ha.y, aRA);
            aRA = fmaf(wr.z, ha.z, aRA); aRA = fmaf(wr.w, ha.w, aRA);
            aZA = fmaf(wz.x, ha.x, aZA); aZA = fmaf(wz.y, ha.y, aZA);
            aZA = fmaf(wz.z, ha.z, aZA); aZA = fmaf(wz.w, ha.w, aZA);
            aNA = fmaf(wn.x, ha.x, aNA); aNA = fmaf(wn.y, ha.y, aNA);
            aNA = fmaf(wn.z, ha.z, aNA); aNA = fmaf(wn.w, ha.w, aNA);
            aRB = fmaf(wr.x, hb.x, aRB); aRB = fmaf(wr.y, hb.y, aRB);
            aRB = fmaf(wr.z, hb.z, aRB); aRB = fmaf(wr.w, hb.w, aRB);
            aZB = fmaf(wz.x, hb.x, aZB); aZB = fmaf(wz.y, hb.y, aZB);
            aZB = fmaf(wz.z, hb.z, aZB); aZB = fmaf(wz.w, hb.w, aZB);
            aNB = fmaf(wn.x, hb.x, aNB); aNB = fmaf(wn.y, hb.y, aNB);
            aNB = fmaf(wn.z, hb.z, aNB); aNB = fmaf(wn.w, hb.w, aNB);
        }
        float holdA = hbuf[(cur * 4 + sA) * 256 + dim];
        float holdB = hbuf[(cur * 4 + sB) * 256 + dim];
        float rA = sigm(giRA + aRA + bhr);
        float zA = sigm(giZA + aZA + bhz);
        float nA = tanhf(giNA + rA * (aNA + bhn));
        float hpA = (1.f - zA) * nA + zA * holdA;
        float rB = sigm(giRB + aRB + bhr);
        float zB = sigm(giZB + aZB + bhz);
        float nB = tanhf(giNB + rB * (aNB + bhn));
        float hpB = (1.f - zB) * nB + zB * holdB;

        g_H[((long)(d * W_ + w) * S_ + (s0 + sA)) * HW_ + dim] = hpA;
        g_H[((long)(d * W_ + w) * S_ + (s0 + sB)) * HW_ + dim] = hpB;

        unsigned laA = su32(&hbuf[(nxt * 4 + sA) * 256 + dim]);
        unsigned laB = su32(&hbuf[(nxt * 4 + sB) * 256 + dim]);
#pragma unroll
        for (int tcta = 0; tcta < 4; tcta++) {
            unsigned ra, rb;
            asm volatile("mapa.shared::cluster.u32 %0, %1, %2;" : "=r"(ra) : "r"(laA), "r"(tcta));
            asm volatile("st.shared::cluster.f32 [%0], %1;" :: "r"(ra), "f"(hpA) : "memory");
            asm volatile("mapa.shared::cluster.u32 %0, %1, %2;" : "=r"(rb) : "r"(laB), "r"(tcta));
            asm volatile("st.shared::cluster.f32 [%0], %1;" :: "r"(rb), "f"(hpB) : "memory");
        }
        asm volatile("barrier.cluster.arrive.aligned;" ::: "memory");  // release
        asm volatile("barrier.cluster.wait.aligned;"   ::: "memory");  // acquire
    }
}

// ---------------- 4. build wordenc = concat(H_fwd, H_bwd) ------------------
__global__ void k_we() {
    int q  = blockIdx.x * blockDim.x + threadIdx.x;   // over 1048576 float4s
    int c4 = q & 127;
    int r  = q >> 7;
    int w  = r & 127, s = r >> 7;
    int d  = c4 >> 6, hw4 = c4 & 63;
    ((float4*)g_WE)[q] = ((const float4*)g_H)[(((d * W_ + w) * S_ + s) << 6) + hw4];
}

// ---------------- 5. sent_summ = sum_w u_word ------------------------------
__global__ void k_sumw() {
    int s = blockIdx.x, n = threadIdx.x;  // 512 threads
    float a = 0.f;
    for (int w = 0; w < W_; w++) a += g_U[((s * W_ + w) << 9) + n];
    g_ssum[(s << 9) + n] = a;
}

// ---------------- 6. sentence encoder pointwise (h0 = 0) -------------------
__global__ void k_sentenc(const float* __restrict__ sbh) {
    int idx = blockIdx.x * blockDim.x + threadIdx.x;  // 65536
    int d = idx >> 15;
    int s = (idx >> 9) & 63;
    int h = idx & 511;
    const float* gi = &g_GIS[(d * S_ + s) * G3S_];
    float r  = sigm(gi[h]       + sbh[d * G3S_ + h]);
    float zz = sigm(gi[512 + h] + sbh[d * G3S_ + 512 + h]);
    float n  = tanhf(gi[1024 + h] + r * sbh[d * G3S_ + 1024 + h]);
    g_SE[s * 1024 + d * 512 + h] = (1.f - zz) * n;
}

// ---------------- 7. outputs -----------------------------------------------
__global__ void k_ones(float* out, int n) {
    int i = blockIdx.x * 256 + threadIdx.x;
    if (i < n) out[i] = 1.0f;   // word_w and sent_w: softmax over size-1 axis == 1
}

__global__ void k_final(const float* __restrict__ doW, const float* __restrict__ dob,
                        float* __restrict__ out, int out_size) {
    __shared__ float doc[1024];
    __shared__ float red[256];
    __shared__ float logit[16];
    int t = threadIdx.x;
    for (int n = t; n < 1024; n += 256) {
        float a = 0.f;
        for (int s = 0; s < S_; s++) a += g_US[s * 1024 + n];
        doc[n] = a;
    }
    __syncthreads();
    for (int c = 0; c < C_; c++) {
        float p = 0.f;
        for (int n = t; n < 1024; n += 256) p = fmaf(doc[n], doW[c * 1024 + n], p);
        red[t] = p; __syncthreads();
        for (int st = 128; st > 0; st >>= 1) {
            if (t < st) red[t] += red[t + st];
            __syncthreads();
        }
        if (t == 0) logit[c] = red[0] + dob[c];
        __syncthreads();
    }
    if (t == 0) {
        float m = -1e30f;
        for (int c = 0; c < C_; c++) m = fmaxf(m, logit[c]);
        float se = 0.f;
        for (int c = 0; c < C_; c++) se += expf(logit[c] - m);
        float lse = m + logf(se);
        for (int c = 0; c < C_; c++) out[out_size - C_ + c] = logit[c] - lse;
    }
}

// ---------------- launcher -------------------------------------------------
extern "C" void kernel_launch(void* const* d_in, const int* in_sizes, int n_in,
                              void* d_out, int out_size) {
    const int*   doc = (const int*)  d_in[0];
    const float* emb = (const float*)d_in[1];
    const float* wWi = (const float*)d_in[2];
    const float* wWh = (const float*)d_in[3];
    const float* wbi = (const float*)d_in[4];
    const float* wbh = (const float*)d_in[5];
    const float* sWi = (const float*)d_in[6];
    const float* sbi = (const float*)d_in[8];
    const float* sbh = (const float*)d_in[9];
    const float* waW = (const float*)d_in[10];
    const float* wab = (const float*)d_in[11];
    const float* saW = (const float*)d_in[13];
    const float* sab = (const float*)d_in[14];
    const float* doW = (const float*)d_in[16];
    const float* dob = (const float*)d_in[17];
    float* out = (float*)d_out;

    cudaFuncSetAttribute(k_wordgru, cudaFuncAttributeMaxDynamicSharedMemorySize, GRU_SMEM);

    float *pX, *pGI, *pWE, *pU, *pS, *pGIS, *pSE, *pUS;
    cudaGetSymbolAddress((void**)&pX,  g_X);
    cudaGetSymbolAddress((void**)&pGI, g_GI);
    cudaGetSymbolAddress((void**)&pWE, g_WE);
    cudaGetSymbolAddress((void**)&pU,  g_U);
    cudaGetSymbolAddress((void**)&pS,  g_ssum);
    cudaGetSymbolAddress((void**)&pGIS,g_GIS);
    cudaGetSymbolAddress((void**)&pSE, g_SE);
    cudaGetSymbolAddress((void**)&pUS, g_US);

    // 1. gather embeddings: X[w][s][:] = emb[doc[s][w]]
    k_gather<<<2048, 256>>>(doc, emb);

    // 2. GI[d] = X @ wWi[d].T + wbi[d]   (M=8192, N=768, K=256)
    k_gemm<<<dim3(128, 12, 2), 256>>>(pX, wWi, wbi, pGI, 8192, 768, 256, 0,
                                      0, 768L * 256, 768, 8192L * 768);

    // 3. recurrence -> g_H
    k_wordgru<<<128, 128, GRU_SMEM>>>(wWh, wbh);

    // 4. wordenc
    k_we<<<4096, 256>>>();

    // 5. u_word = tanh(wordenc @ waW.T + wab)   (M=8192, N=512, K=512)
    k_gemm<<<dim3(128, 8, 1), 256>>>(pWE, waW, wab, pU, 8192, 512, 512, 1, 0, 0, 0, 0);

    // 6. sent_summ = sum_w u_word
    k_sumw<<<64, 512>>>();

    // 7. GIS[d] = sent_summ @ sWi[d].T + sbi[d]  (M=64, N=1536, K=512)
    k_gemm<<<dim3(1, 24, 2), 256>>>(pS, sWi, sbi, pGIS, 64, 1536, 512, 0,
                                    0, 1536L * 512, 1536, 64L * 1536);

    // 8. sentenc pointwise
    k_sentenc<<<256, 256>>>(sbh);

    // 9. u_sent = tanh(sentenc @ saW.T + sab)   (M=64, N=1024, K=1024)
    k_gemm<<<dim3(1, 16, 1), 256>>>(pSE, saW, sab, pUS, 64, 1024, 1024, 1, 0, 0, 0, 0);

    // 10. outputs
    int nOnes = out_size - C_;
    k_ones<<<(nOnes + 255) / 256, 256>>>(out, nOnes);
    k_final<<<1, 256>>>(doW, dob, out, out_size);
}

// round 4
// speedup vs baseline: 1.2239x; 1.2239x over previous
#include <cuda_runtime.h>
#include <cstdint>

#define S_   64
#define W_   128
#define D_   256
#define HW_  256
#define G3W_ 768
#define HS_  512
#define G3S_ 1536
#define C_   13

// ---------------- scratch (device globals; no allocation allowed) ----------
__device__ float g_X [2097152];    // [w][s][d]           128*64*256
__device__ float g_GI[12582912];   // [d][w][s][768]      2*128*64*768
__device__ float g_H [4194304];    // [d][w][s][256]
__device__ float g_ssum[S_*HS_];         // [s][512]
__device__ float g_GIS[2*S_*G3S_];       // [d][s][1536]
__device__ float g_SE[S_*1024];          // [s][1024]
__device__ float g_US[S_*1024];          // [s][1024]

// ---------------- helpers --------------------------------------------------
__device__ __forceinline__ unsigned su32(const void* p) {
    return (unsigned)__cvta_generic_to_shared(p);
}
__device__ __forceinline__ float sigm(float x) { return 1.f / (1.f + expf(-x)); }

// ---------------- 1. embedding gather --------------------------------------
__global__ void k_gather(const int* __restrict__ doc, const float* __restrict__ emb) {
    int q  = blockIdx.x * blockDim.x + threadIdx.x;   // over 524288 float4s
    int d4 = q & 63;
    int rs = q >> 6;            // = w*64 + s
    int s  = rs & 63, w = rs >> 6;
    int tok = doc[s * W_ + w];
    ((float4*)g_X)[q] = ((const float4*)emb)[(long)tok * 64 + d4];
}

// ---------------- 2a. fast 128x128x8 SGEMM: C = A @ B^T + bias -------------
// A[M,K] row-major, B[N,K] row-major (torch weight layout). batch z.
// 256 threads, 8x8 microtile (4+4 split), double-buffered SMEM, LDS.128.
__global__ __launch_bounds__(256, 2) void k_gemm128(
    const float* __restrict__ A, const float* __restrict__ B,
    const float* __restrict__ bias, float* __restrict__ C,
    int M, int N, int K,
    long sAz, long sBz, long sbz, long sCz)
{
    __shared__ float As[2][1056];   // [8][132] x 2
    __shared__ float Bs[2][1056];
    int t  = threadIdx.x;
    int z  = blockIdx.z;
    const float* Ab = A + z * sAz + (long)blockIdx.x * 128 * K;
    const float* Bb = B + z * sBz + (long)blockIdx.y * 128 * K;
    int r  = t >> 1;            // 0..127
    int kc = (t & 1) * 4;       // 0 or 4
    int tx = t & 15, ty = t >> 4;

    float4 av = *(const float4*)&Ab[(long)r * K + kc];
    float4 bv = *(const float4*)&Bb[(long)r * K + kc];
    As[0][(kc+0)*132+r] = av.x; As[0][(kc+1)*132+r] = av.y;
    As[0][(kc+2)*132+r] = av.z; As[0][(kc+3)*132+r] = av.w;
    Bs[0][(kc+0)*132+r] = bv.x; Bs[0][(kc+1)*132+r] = bv.y;
    Bs[0][(kc+2)*132+r] = bv.z; Bs[0][(kc+3)*132+r] = bv.w;
    __syncthreads();

    float acc[8][8] = {};
    int nb = K >> 3;
    for (int kb = 0; kb < nb; kb++) {
        if (kb + 1 < nb) {
            av = *(const float4*)&Ab[(long)r * K + (kb + 1) * 8 + kc];
            bv = *(const float4*)&Bb[(long)r * K + (kb + 1) * 8 + kc];
        }
        const float* Ac = As[kb & 1];
        const float* Bc = Bs[kb & 1];
#pragma unroll
        for (int k = 0; k < 8; k++) {
            float4 a0 = *(const float4*)&Ac[k*132 + ty*4];
            float4 a1 = *(const float4*)&Ac[k*132 + 64 + ty*4];
            float4 b0 = *(const float4*)&Bc[k*132 + tx*4];
            float4 b1 = *(const float4*)&Bc[k*132 + 64 + tx*4];
            float a[8] = {a0.x,a0.y,a0.z,a0.w,a1.x,a1.y,a1.z,a1.w};
            float b[8] = {b0.x,b0.y,b0.z,b0.w,b1.x,b1.y,b1.z,b1.w};
#pragma unroll
            for (int i = 0; i < 8; i++)
#pragma unroll
                for (int j = 0; j < 8; j++)
                    acc[i][j] = fmaf(a[i], b[j], acc[i][j]);
        }
        if (kb + 1 < nb) {
            int nx = (kb + 1) & 1;
            As[nx][(kc+0)*132+r] = av.x; As[nx][(kc+1)*132+r] = av.y;
            As[nx][(kc+2)*132+r] = av.z; As[nx][(kc+3)*132+r] = av.w;
            Bs[nx][(kc+0)*132+r] = bv.x; Bs[nx][(kc+1)*132+r] = bv.y;
            Bs[nx][(kc+2)*132+r] = bv.z; Bs[nx][(kc+3)*132+r] = bv.w;
        }
        __syncthreads();
    }

    const float* bp = bias + z * sbz + blockIdx.y * 128;
    float4 bq0 = *(const float4*)&bp[tx*4];
    float4 bq1 = *(const float4*)&bp[64 + tx*4];
#pragma unroll
    for (int i = 0; i < 8; i++) {
        int m = blockIdx.x * 128 + ((i < 4) ? ty*4 + i : 64 + ty*4 + (i-4));
        long base = z * sCz + (long)m * N + blockIdx.y * 128;
        float4 o0, o1;
        o0.x = acc[i][0]+bq0.x; o0.y = acc[i][1]+bq0.y;
        o0.z = acc[i][2]+bq0.z; o0.w = acc[i][3]+bq0.w;
        o1.x = acc[i][4]+bq1.x; o1.y = acc[i][5]+bq1.y;
        o1.z = acc[i][6]+bq1.z; o1.w = acc[i][7]+bq1.w;
        *(float4*)&C[base + tx*4]      = o0;
        *(float4*)&C[base + 64 + tx*4] = o1;
    }
}

// ---------------- 2b. fused word attention + sum over words ----------------
// Computes tanh(wordenc @ waW.T + wab) for one sentence (128 words = M-tile)
// and reduces over words in the epilogue: writes g_ssum[s][ncols].
// wordenc[s,w,k] = g_H[(dir*128 + w)*64 + s][hw]  with dir=k>>8, hw=k&255.
__global__ __launch_bounds__(256, 2) void k_uword(
    const float* __restrict__ waW, const float* __restrict__ wab)
{
    __shared__ float As[2][1056];
    __shared__ float Bs[2][1056];
    int t  = threadIdx.x;
    int s  = blockIdx.x;                 // sentence
    const float* Bb = waW + (long)blockIdx.y * 128 * HS_;
    int r  = t >> 1;                     // 0..127 (= word index for A)
    int kc = (t & 1) * 4;
    int tx = t & 15, ty = t >> 4;

    // A loader: row r = word w, column k -> g_H
    auto loadA = [&](int k0) -> float4 {
        int k   = k0 + kc;
        int dir = k >> 8;
        int hw  = k & 255;
        return *(const float4*)&g_H[((long)(dir * W_ + r) * S_ + s) * HW_ + hw];
    };

    float4 av = loadA(0);
    float4 bv = *(const float4*)&Bb[(long)r * HS_ + kc];
    As[0][(kc+0)*132+r] = av.x; As[0][(kc+1)*132+r] = av.y;
    As[0][(kc+2)*132+r] = av.z; As[0][(kc+3)*132+r] = av.w;
    Bs[0][(kc+0)*132+r] = bv.x; Bs[0][(kc+1)*132+r] = bv.y;
    Bs[0][(kc+2)*132+r] = bv.z; Bs[0][(kc+3)*132+r] = bv.w;
    __syncthreads();

    float acc[8][8] = {};
    const int nb = HS_ >> 3;   // 64
    for (int kb = 0; kb < nb; kb++) {
        if (kb + 1 < nb) {
            av = loadA((kb + 1) * 8);
            bv = *(const float4*)&Bb[(long)r * HS_ + (kb + 1) * 8 + kc];
        }
        const float* Ac = As[kb & 1];
        const float* Bc = Bs[kb & 1];
#pragma unroll
        for (int k = 0; k < 8; k++) {
            float4 a0 = *(const float4*)&Ac[k*132 + ty*4];
            float4 a1 = *(const float4*)&Ac[k*132 + 64 + ty*4];
            float4 b0 = *(const float4*)&Bc[k*132 + tx*4];
            float4 b1 = *(const float4*)&Bc[k*132 + 64 + tx*4];
            float a[8] = {a0.x,a0.y,a0.z,a0.w,a1.x,a1.y,a1.z,a1.w};
            float b[8] = {b0.x,b0.y,b0.z,b0.w,b1.x,b1.y,b1.z,b1.w};
#pragma unroll
            for (int i = 0; i < 8; i++)
#pragma unroll
                for (int j = 0; j < 8; j++)
                    acc[i][j] = fmaf(a[i], b[j], acc[i][j]);
        }
        if (kb + 1 < nb) {
            int nx = (kb + 1) & 1;
            As[nx][(kc+0)*132+r] = av.x; As[nx][(kc+1)*132+r] = av.y;
            As[nx][(kc+2)*132+r] = av.z; As[nx][(kc+3)*132+r] = av.w;
            Bs[nx][(kc+0)*132+r] = bv.x; Bs[nx][(kc+1)*132+r] = bv.y;
            Bs[nx][(kc+2)*132+r] = bv.z; Bs[nx][(kc+3)*132+r] = bv.w;
        }
        __syncthreads();
    }

    // epilogue: v = tanh(acc + bias); per-thread sum over its 8 rows,
    // then cross-ty reduction in SMEM -> g_ssum[s][n0 + col]
    const float* bp = wab + blockIdx.y * 128;
    float rsum[8];
#pragma unroll
    for (int j = 0; j < 8; j++) {
        int col = (j < 4) ? tx*4 + j : 64 + tx*4 + (j-4);
        float bj = bp[col];
        float sum = 0.f;
#pragma unroll
        for (int i = 0; i < 8; i++) sum += tanhf(acc[i][j] + bj);
        rsum[j] = sum;
    }
    __syncthreads();                      // done with As; reuse as reduction buf
    float* red = &As[0][0];               // [16][132]
#pragma unroll
    for (int j = 0; j < 8; j++) {
        int col = (j < 4) ? tx*4 + j : 64 + tx*4 + (j-4);
        red[ty*132 + col] = rsum[j];
    }
    __syncthreads();
    if (t < 128) {
        float a = 0.f;
#pragma unroll
        for (int y = 0; y < 16; y++) a += red[y*132 + t];
        g_ssum[s * HS_ + blockIdx.y * 128 + t] = a;
    }
}

// ---------------- 2c. small generic GEMM (M=64 cases) ----------------------
#define BM 64
#define BN 64
#define BK 32
__global__ __launch_bounds__(256) void k_gemm(
    const float* __restrict__ A, const float* __restrict__ B,
    const float* __restrict__ bias, float* __restrict__ C,
    int M, int N, int K, int actTanh,
    long sAz, long sBz, long sbz, long sCz)
{
    __shared__ float As2[BK][BM + 1];
    __shared__ float Bs2[BK][BN + 1];
    int t  = threadIdx.x;
    int tx = t & 15, ty = t >> 4;
    int z  = blockIdx.z;
    const float* Ab = A + z * sAz + (long)blockIdx.x * BM * K;
    const float* Bb = B + z * sBz + (long)blockIdx.y * BN * K;
    float acc[4][4] = {};
    for (int k0 = 0; k0 < K; k0 += BK) {
#pragma unroll
        for (int j = 0; j < 8; j++) {
            int idx = j * 256 + t;
            int m = idx >> 5, k = idx & 31;
            As2[k][m] = Ab[(long)m * K + k0 + k];
            Bs2[k][m] = Bb[(long)m * K + k0 + k];
        }
        __syncthreads();
#pragma unroll 8
        for (int k = 0; k < BK; k++) {
            float a0 = As2[k][ty*4+0], a1 = As2[k][ty*4+1], a2 = As2[k][ty*4+2], a3 = As2[k][ty*4+3];
            float b0 = Bs2[k][tx*4+0], b1 = Bs2[k][tx*4+1], b2 = Bs2[k][tx*4+2], b3 = Bs2[k][tx*4+3];
            acc[0][0]=fmaf(a0,b0,acc[0][0]); acc[0][1]=fmaf(a0,b1,acc[0][1]);
            acc[0][2]=fmaf(a0,b2,acc[0][2]); acc[0][3]=fmaf(a0,b3,acc[0][3]);
            acc[1][0]=fmaf(a1,b0,acc[1][0]); acc[1][1]=fmaf(a1,b1,acc[1][1]);
            acc[1][2]=fmaf(a1,b2,acc[1][2]); acc[1][3]=fmaf(a1,b3,acc[1][3]);
            acc[2][0]=fmaf(a2,b0,acc[2][0]); acc[2][1]=fmaf(a2,b1,acc[2][1]);
            acc[2][2]=fmaf(a2,b2,acc[2][2]); acc[2][3]=fmaf(a2,b3,acc[2][3]);
            acc[3][0]=fmaf(a3,b0,acc[3][0]); acc[3][1]=fmaf(a3,b1,acc[3][1]);
            acc[3][2]=fmaf(a3,b2,acc[3][2]); acc[3][3]=fmaf(a3,b3,acc[3][3]);
        }
        __syncthreads();
    }
    const float* bp = bias + z * sbz;
#pragma unroll
    for (int i = 0; i < 4; i++) {
        int m = blockIdx.x * BM + ty * 4 + i;
#pragma unroll
        for (int j = 0; j < 4; j++) {
            int n = blockIdx.y * BN + tx * 4 + j;
            float v = acc[i][j] + bp[n];
            if (actTanh) v = tanhf(v);
            C[z * sCz + (long)m * N + n] = v;
        }
    }
}

// ---------------- 3. word GRU recurrence (cluster of 4) --------------------
#define PADK 260                                    // 260 % 32 == 4 -> conflict-free LDS.128
#define GRU_SMEM ((3*64*PADK + 2*4*256 + 192) * 4)  // 208640 B

extern __shared__ float smem_gru[];

__global__ void __cluster_dims__(4, 1, 1) __launch_bounds__(128, 1)
k_wordgru(const float* __restrict__ wWh, const float* __restrict__ wbh)
{
    float* Wsh  = smem_gru;                 // [3*64][PADK]
    float* hbuf = Wsh + 3 * 64 * PADK;      // [2][4][256]
    float* bhs  = hbuf + 2 * 4 * 256;       // [192]

    int rank = blockIdx.x & 3;
    int cid  = blockIdx.x >> 2;
    int d    = cid >> 4;
    int s0   = (cid & 15) * 4;
    int j0   = rank * 64;
    int tid  = threadIdx.x;

    const float4* w4g = (const float4*)wWh;
    for (int i = tid; i < 3 * 64 * 64; i += 128) {
        int g  = i >> 12;
        int r2 = i & 4095;
        int jj = r2 >> 6, k4 = r2 & 63;
        float4 v = w4g[((long)d * G3W_ + g * 256 + j0 + jj) * 64 + k4];
        *(float4*)&Wsh[(g * 64 + jj) * PADK + k4 * 4] = v;
    }
    for (int i = tid; i < 192; i += 128)
        bhs[i] = wbh[d * G3W_ + (i >> 6) * 256 + j0 + (i & 63)];
    for (int i = tid; i < 4 * 256; i += 128) hbuf[i] = 0.f;
    __syncthreads();
    asm volatile("barrier.cluster.arrive.aligned;" ::: "memory");
    asm volatile("barrier.cluster.wait.aligned;"   ::: "memory");

    int spair = tid >> 6;
    int jj    = tid & 63;
    int sA = spair * 2, sB = sA + 1;
    int dim = j0 + jj;
    float bhr = bhs[jj], bhz = bhs[64 + jj], bhn = bhs[128 + jj];
    const float4* wR = (const float4*)&Wsh[( 0 + jj) * PADK];
    const float4* wZ = (const float4*)&Wsh[( 64 + jj) * PADK];
    const float4* wN = (const float4*)&Wsh[(128 + jj) * PADK];

    for (int w = 0; w < W_; w++) {
        int cur = w & 1, nxt = cur ^ 1;
        long gibA = ((long)(d * W_ + w) * S_ + (s0 + sA)) * G3W_;
        long gibB = ((long)(d * W_ + w) * S_ + (s0 + sB)) * G3W_;
        float giRA = g_GI[gibA + dim], giZA = g_GI[gibA + 256 + dim], giNA = g_GI[gibA + 512 + dim];
        float giRB = g_GI[gibB + dim], giZB = g_GI[gibB + 256 + dim], giNB = g_GI[gibB + 512 + dim];

        const float4* hA = (const float4*)&hbuf[(cur * 4 + sA) * 256];
        const float4* hB = (const float4*)&hbuf[(cur * 4 + sB) * 256];
        float aRA = 0, aZA = 0, aNA = 0, aRB = 0, aZB = 0, aNB = 0;
#pragma unroll 8
        for (int k4 = 0; k4 < 64; k4++) {
            float4 wr = wR[k4], wz = wZ[k4], wn = wN[k4];
            float4 ha = hA[k4], hb = hB[k4];
            aRA = fmaf(wr.x, ha.x, aRA); aRA = fmaf(wr.y, ha.y, aRA);
            aRA = fmaf(wr.z, ha.z, aRA); aRA = fmaf(wr.w, ha.w, aRA);
            aZA = fmaf(wz.x, ha.x, aZA); aZA = fmaf(wz.y, ha.y, aZA);
            aZA = fmaf(wz.z, ha.z, aZA); aZA = fmaf(wz.w, ha.w, aZA);
            aNA = fmaf(wn.x, ha.x, aNA); aNA = fmaf(wn.y, ha.y, aNA);
            aNA = fmaf(wn.z, ha.z, aNA); aNA = fmaf(wn.w, ha.w, aNA);
            aRB = fmaf(wr.x, hb.x, aRB); aRB = fmaf(wr.y, hb.y, aRB);
            aRB = fmaf(wr.z, hb.z, aRB); aRB = fmaf(wr.w, hb.w, aRB);
            aZB = fmaf(wz.x, hb.x, aZB); aZB = fmaf(wz.y, hb.y, aZB);
            aZB = fmaf(wz.z, hb.z, aZB); aZB = fmaf(wz.w, hb.w, aZB);
            aNB = fmaf(wn.x, hb.x, aNB); aNB = fmaf(wn.y, hb.y, aNB);
            aNB = fmaf(wn.z, hb.z, aNB); aNB = fmaf(wn.w, hb.w, aNB);
        }
        float holdA = hbuf[(cur * 4 + sA) * 256 + dim];
        float holdB = hbuf[(cur * 4 + sB) * 256 + dim];
        float rA = sigm(giRA + aRA + bhr);
        float zA = sigm(giZA + aZA + bhz);
        float nA = tanhf(giNA + rA * (aNA + bhn));
        float hpA = (1.f - zA) * nA + zA * holdA;
        float rB = sigm(giRB + aRB + bhr);
        float zB = sigm(giZB + aZB + bhz);
        float nB = tanhf(giNB + rB * (aNB + bhn));
        float hpB = (1.f - zB) * nB + zB * holdB;

        g_H[((long)(d * W_ + w) * S_ + (s0 + sA)) * HW_ + dim] = hpA;
        g_H[((long)(d * W_ + w) * S_ + (s0 + sB)) * HW_ + dim] = hpB;

        unsigned laA = su32(&hbuf[(nxt * 4 + sA) * 256 + dim]);
        unsigned laB = su32(&hbuf[(nxt * 4 + sB) * 256 + dim]);
#pragma unroll
        for (int tcta = 0; tcta < 4; tcta++) {
            unsigned ra, rb;
            asm volatile("mapa.shared::cluster.u32 %0, %1, %2;" : "=r"(ra) : "r"(laA), "r"(tcta));
            asm volatile("st.shared::cluster.f32 [%0], %1;" :: "r"(ra), "f"(hpA) : "memory");
            asm volatile("mapa.shared::cluster.u32 %0, %1, %2;" : "=r"(rb) : "r"(laB), "r"(tcta));
            asm volatile("st.shared::cluster.f32 [%0], %1;" :: "r"(rb), "f"(hpB) : "memory");
        }
        asm volatile("barrier.cluster.arrive.aligned;" ::: "memory");
        asm volatile("barrier.cluster.wait.aligned;"   ::: "memory");
    }
}

// ---------------- 6. sentence encoder pointwise (h0 = 0) -------------------
__global__ void k_sentenc(const float* __restrict__ sbh) {
    int idx = blockIdx.x * blockDim.x + threadIdx.x;  // 65536
    int d = idx >> 15;
    int s = (idx >> 9) & 63;
    int h = idx & 511;
    const float* gi = &g_GIS[(d * S_ + s) * G3S_];
    float r  = sigm(gi[h]       + sbh[d * G3S_ + h]);
    float zz = sigm(gi[512 + h] + sbh[d * G3S_ + 512 + h]);
    float n  = tanhf(gi[1024 + h] + r * sbh[d * G3S_ + 1024 + h]);
    g_SE[s * 1024 + d * 512 + h] = (1.f - zz) * n;
}

// ---------------- 7. outputs -----------------------------------------------
__global__ void k_ones(float* out, int n) {
    int i = blockIdx.x * 256 + threadIdx.x;
    if (i < n) out[i] = 1.0f;
}

__global__ void k_final(const float* __restrict__ doW, const float* __restrict__ dob,
                        float* __restrict__ out, int out_size) {
    __shared__ float doc[1024];
    __shared__ float red[256];
    __shared__ float logit[16];
    int t = threadIdx.x;
    for (int n = t; n < 1024; n += 256) {
        float a = 0.f;
        for (int s = 0; s < S_; s++) a += g_US[s * 1024 + n];
        doc[n] = a;
    }
    __syncthreads();
    for (int c = 0; c < C_; c++) {
        float p = 0.f;
        for (int n = t; n < 1024; n += 256) p = fmaf(doc[n], doW[c * 1024 + n], p);
        red[t] = p; __syncthreads();
        for (int st = 128; st > 0; st >>= 1) {
            if (t < st) red[t] += red[t + st];
            __syncthreads();
        }
        if (t == 0) logit[c] = red[0] + dob[c];
        __syncthreads();
    }
    if (t == 0) {
        float m = -1e30f;
        for (int c = 0; c < C_; c++) m = fmaxf(m, logit[c]);
        float se = 0.f;
        for (int c = 0; c < C_; c++) se += expf(logit[c] - m);
        float lse = m + logf(se);
        for (int c = 0; c < C_; c++) out[out_size - C_ + c] = logit[c] - lse;
    }
}

// ---------------- launcher -------------------------------------------------
extern "C" void kernel_launch(void* const* d_in, const int* in_sizes, int n_in,
                              void* d_out, int out_size) {
    const int*   doc = (const int*)  d_in[0];
    const float* emb = (const float*)d_in[1];
    const float* wWi = (const float*)d_in[2];
    const float* wWh = (const float*)d_in[3];
    const float* wbi = (const float*)d_in[4];
    const float* wbh = (const float*)d_in[5];
    const float* sWi = (const float*)d_in[6];
    const float* sbi = (const float*)d_in[8];
    const float* sbh = (const float*)d_in[9];
    const float* waW = (const float*)d_in[10];
    const float* wab = (const float*)d_in[11];
    const float* saW = (const float*)d_in[13];
    const float* sab = (const float*)d_in[14];
    const float* doW = (const float*)d_in[16];
    const float* dob = (const float*)d_in[17];
    float* out = (float*)d_out;

    cudaFuncSetAttribute(k_wordgru, cudaFuncAttributeMaxDynamicSharedMemorySize, GRU_SMEM);

    float *pX, *pGI, *pS, *pGIS, *pSE, *pUS;
    cudaGetSymbolAddress((void**)&pX,  g_X);
    cudaGetSymbolAddress((void**)&pGI, g_GI);
    cudaGetSymbolAddress((void**)&pS,  g_ssum);
    cudaGetSymbolAddress((void**)&pGIS,g_GIS);
    cudaGetSymbolAddress((void**)&pSE, g_SE);
    cudaGetSymbolAddress((void**)&pUS, g_US);

    // 1. gather embeddings: X[w][s][:] = emb[doc[s][w]]
    k_gather<<<2048, 256>>>(doc, emb);

    // 2. GI[d] = X @ wWi[d].T + wbi[d]   (M=8192, N=768, K=256)
    k_gemm128<<<dim3(64, 6, 2), 256>>>(pX, wWi, wbi, pGI, 8192, 768, 256,
                                       0, 768L * 256, 768, 8192L * 768);

    // 3. recurrence -> g_H
    k_wordgru<<<128, 128, GRU_SMEM>>>(wWh, wbh);

    // 4+5+6 fused: g_ssum[s] = sum_w tanh(wordenc[s,w] @ waW.T + wab)
    k_uword<<<dim3(64, 4), 256>>>(waW, wab);

    // 7. GIS[d] = sent_summ @ sWi[d].T + sbi[d]  (M=64, N=1536, K=512)
    k_gemm<<<dim3(1, 24, 2), 256>>>(pS, sWi, sbi, pGIS, 64, 1536, 512, 0,
                                    0, 1536L * 512, 1536, 64L * 1536);

    // 8. sentenc pointwise
    k_sentenc<<<256, 256>>>(sbh);

    // 9. u_sent = tanh(sentenc @ saW.T + sab)   (M=64, N=1024, K=1024)
    k_gemm<<<dim3(1, 16, 1), 256>>>(pSE, saW, sab, pUS, 64, 1024, 1024, 1, 0, 0, 0, 0);

    // 10. outputs
    int nOnes = out_size - C_;
    k_ones<<<(nOnes + 255) / 256, 256>>>(out, nOnes);
    k_final<<<1, 256>>>(doW, dob, out, out_size);
}